// round 1
// baseline (speedup 1.0000x reference)
#include <cuda_runtime.h>

// Problem constants
#define BB 8
#define SS 1024
#define DD 768
#define HH 16
#define HD 48
#define TOK (BB*SS)          // 8192
#define BHN (BB*HH)          // 128

// Scratch (static device arrays — no allocation allowed)
__device__ __align__(256) float g_q[BHN*SS*HD];
__device__ __align__(256) float g_k[BHN*SS*HD];
__device__ __align__(256) float g_v[BHN*SS*HD];
__device__ __align__(256) float g_ao[TOK*DD];

// ---------------------------------------------------------------------------
// Tiled fp32 GEMM body: C[64x64] tile of A[TOK,768] @ W[768,768]
// 256 threads, 4x4 register tile per thread, BK=16.
// As stored transposed [16][65] (padded), Bs [16][64].
// ---------------------------------------------------------------------------
__device__ __forceinline__ void gemm_body(const float* __restrict__ A,
                                          const float* __restrict__ W,
                                          float* As, float* Bs,
                                          float acc[4][4],
                                          int m0, int n0)
{
    const int tid = threadIdx.x;
    const int tx = tid & 15, ty = tid >> 4;
    for (int kt = 0; kt < DD / 16; ++kt) {
        const int k0 = kt * 16;
        // Load A tile 64x16 -> As[k][m] (transposed, stride 65)
        {
            int e = tid * 4;
            int row = e >> 4, k = e & 15;
            float4 va = *reinterpret_cast<const float4*>(
                &A[(size_t)(m0 + row) * DD + k0 + k]);
            As[(k + 0) * 65 + row] = va.x;
            As[(k + 1) * 65 + row] = va.y;
            As[(k + 2) * 65 + row] = va.z;
            As[(k + 3) * 65 + row] = va.w;
        }
        // Load B tile 16x64 -> Bs[k][c]
        {
            int e = tid * 4;
            int k = e >> 6, c = e & 63;
            *reinterpret_cast<float4*>(&Bs[k * 64 + c]) =
                *reinterpret_cast<const float4*>(
                    &W[(size_t)(k0 + k) * DD + n0 + c]);
        }
        __syncthreads();
        #pragma unroll
        for (int kk = 0; kk < 16; ++kk) {
            float a[4], b[4];
            #pragma unroll
            for (int i = 0; i < 4; ++i) a[i] = As[kk * 65 + ty * 4 + i];
            #pragma unroll
            for (int j = 0; j < 4; ++j) b[j] = Bs[kk * 64 + tx * 4 + j];
            #pragma unroll
            for (int i = 0; i < 4; ++i)
                #pragma unroll
                for (int j = 0; j < 4; ++j)
                    acc[i][j] += a[i] * b[j];
        }
        __syncthreads();
    }
}

// ---------------------------------------------------------------------------
// QKV projection: z in {0,1,2} selects (Wq,bq)->g_q, (Wk,bk)->g_k, (Wv,bv)->g_v
// Output remapped to [B*H, S, 48]
// ---------------------------------------------------------------------------
__global__ void qkv_kernel(const float* __restrict__ x,
                           const float* __restrict__ Wq, const float* __restrict__ bq,
                           const float* __restrict__ Wk, const float* __restrict__ bk,
                           const float* __restrict__ Wv, const float* __restrict__ bv)
{
    __shared__ float As[16 * 65];
    __shared__ float Bs[16 * 64];
    const int z = blockIdx.z;
    const float* W    = (z == 0) ? Wq : (z == 1) ? Wk : Wv;
    const float* bias = (z == 0) ? bq : (z == 1) ? bk : bv;
    float* out        = (z == 0) ? g_q : (z == 1) ? g_k : g_v;

    float acc[4][4] = {};
    const int m0 = blockIdx.x * 64, n0 = blockIdx.y * 64;
    gemm_body(x, W, As, Bs, acc, m0, n0);

    const int tx = threadIdx.x & 15, ty = threadIdx.x >> 4;
    #pragma unroll
    for (int i = 0; i < 4; ++i) {
        const int t = m0 + ty * 4 + i;
        const int b = t >> 10, s = t & 1023;
        #pragma unroll
        for (int j = 0; j < 4; ++j) {
            const int c = n0 + tx * 4 + j;
            const int h = c / HD, hd = c % HD;
            out[(((size_t)(b * HH + h)) * SS + s) * HD + hd] = acc[i][j] + bias[c];
        }
    }
}

// ---------------------------------------------------------------------------
// Output projection: g_ao [TOK,768] @ Wo + bo -> d_out
// ---------------------------------------------------------------------------
__global__ void oproj_kernel(const float* __restrict__ Wo,
                             const float* __restrict__ bo,
                             float* __restrict__ out)
{
    __shared__ float As[16 * 65];
    __shared__ float Bs[16 * 64];
    float acc[4][4] = {};
    const int m0 = blockIdx.x * 64, n0 = blockIdx.y * 64;
    gemm_body(g_ao, Wo, As, Bs, acc, m0, n0);

    const int tx = threadIdx.x & 15, ty = threadIdx.x >> 4;
    #pragma unroll
    for (int i = 0; i < 4; ++i) {
        const int r = m0 + ty * 4 + i;
        #pragma unroll
        for (int j = 0; j < 4; ++j) {
            const int c = n0 + tx * 4 + j;
            out[(size_t)r * DD + c] = acc[i][j] + bo[c];
        }
    }
}

// ---------------------------------------------------------------------------
// Flash-style attention. One CTA = (bh, q-tile of 64). 256 threads.
//   Qs  [48][65]  (transposed, padded)
//   KV  shared buffer: K as [48][65] transposed, then V as [64][48]
//   Ps  [64][65]  scores/probs (padded vs 32-way conflict in PV reads)
// Online softmax, O accumulated in registers (12 floats/thread).
// ---------------------------------------------------------------------------
__global__ void attn_kernel()
{
    __shared__ float Qs[48 * 65];
    __shared__ float KV[48 * 65];   // also holds V as [64][48] (3072 <= 3120)
    __shared__ float Ps[64 * 65];
    __shared__ float sm_m[64], sm_l[64], sm_c[64];

    const int tid = threadIdx.x;
    const int bh = blockIdx.y;
    const int q0 = blockIdx.x * 64;
    const float* qp = g_q + (size_t)bh * SS * HD;
    const float* kp = g_k + (size_t)bh * SS * HD;
    const float* vp = g_v + (size_t)bh * SS * HD;

    // Load Q tile transposed
    for (int e = tid; e < 64 * 48; e += 256) {
        int r = e / 48, d = e % 48;
        Qs[d * 65 + r] = qp[(size_t)(q0 + r) * HD + d];
    }
    if (tid < 64) { sm_m[tid] = -1e30f; sm_l[tid] = 0.f; }

    const int tx = tid & 15, ty = tid >> 4;     // score phase mapping
    const int qpv = tid & 63, dg = tid >> 6;    // PV phase mapping
    const int d0 = dg * 12;
    float Oacc[12];
    #pragma unroll
    for (int j = 0; j < 12; ++j) Oacc[j] = 0.f;
    __syncthreads();

    for (int kt = 0; kt < SS / 64; ++kt) {
        // Load K tile transposed into KV
        for (int e = tid; e < 64 * 48; e += 256) {
            int r = e / 48, d = e % 48;
            KV[d * 65 + r] = kp[(size_t)(kt * 64 + r) * HD + d];
        }
        __syncthreads();

        // Scores: S = Q K^T * (1/sqrt(48))
        float sacc[4][4] = {};
        #pragma unroll 4
        for (int d = 0; d < 48; ++d) {
            float a[4], b[4];
            #pragma unroll
            for (int i = 0; i < 4; ++i) a[i] = Qs[d * 65 + ty * 4 + i];
            #pragma unroll
            for (int j = 0; j < 4; ++j) b[j] = KV[d * 65 + tx * 4 + j];
            #pragma unroll
            for (int i = 0; i < 4; ++i)
                #pragma unroll
                for (int j = 0; j < 4; ++j)
                    sacc[i][j] += a[i] * b[j];
        }
        const float sc = 0.14433756729740643f;   // 1/sqrt(48)
        #pragma unroll
        for (int i = 0; i < 4; ++i)
            #pragma unroll
            for (int j = 0; j < 4; ++j)
                Ps[(ty * 4 + i) * 65 + tx * 4 + j] = sacc[i][j] * sc;
        __syncthreads();

        // Load V tile (overwrites K; K no longer needed) — all threads
        for (int e = tid; e < 64 * 48; e += 256) {
            int r = e / 48, d = e % 48;
            KV[r * 48 + d] = vp[(size_t)(kt * 64 + r) * HD + d];
        }
        // Online softmax per row — threads 0..63
        if (tid < 64) {
            const int q = tid;
            float mold = sm_m[q];
            float mx = mold;
            #pragma unroll 8
            for (int k = 0; k < 64; ++k) mx = fmaxf(mx, Ps[q * 65 + k]);
            float sum = 0.f;
            #pragma unroll 8
            for (int k = 0; k < 64; ++k) {
                float p = __expf(Ps[q * 65 + k] - mx);
                Ps[q * 65 + k] = p;
                sum += p;
            }
            float corr = __expf(mold - mx);
            sm_c[q] = corr;
            sm_l[q] = sm_l[q] * corr + sum;
            sm_m[q] = mx;
        }
        __syncthreads();

        // PV: O += P @ V   (thread owns row qpv, cols d0..d0+11)
        const float corr = sm_c[qpv];
        #pragma unroll
        for (int j = 0; j < 12; ++j) Oacc[j] *= corr;
        #pragma unroll 4
        for (int k = 0; k < 64; ++k) {
            const float p = Ps[qpv * 65 + k];
            #pragma unroll
            for (int j = 0; j < 12; ++j)
                Oacc[j] += p * KV[k * 48 + d0 + j];
        }
        __syncthreads();   // before next tile overwrites KV / Ps
    }

    const float linv = 1.0f / sm_l[qpv];
    const int b = bh >> 4, h = bh & 15;
    float* op = g_ao + ((size_t)(b * SS + q0 + qpv)) * DD + h * HD + d0;
    #pragma unroll
    for (int j = 0; j < 12; ++j) op[j] = Oacc[j] * linv;
}

// ---------------------------------------------------------------------------
extern "C" void kernel_launch(void* const* d_in, const int* in_sizes, int n_in,
                              void* d_out, int out_size)
{
    const float* x  = (const float*)d_in[0];
    const float* Wq = (const float*)d_in[1];
    const float* bq = (const float*)d_in[2];
    const float* Wk = (const float*)d_in[3];
    const float* bk = (const float*)d_in[4];
    const float* Wv = (const float*)d_in[5];
    const float* bv = (const float*)d_in[6];
    const float* Wo = (const float*)d_in[7];
    const float* bo = (const float*)d_in[8];
    float* out = (float*)d_out;

    dim3 gq(TOK / 64, DD / 64, 3);
    qkv_kernel<<<gq, 256>>>(x, Wq, bq, Wk, bk, Wv, bv);

    dim3 ga(SS / 64, BHN);
    attn_kernel<<<ga, 256>>>();

    dim3 go(TOK / 64, DD / 64);
    oproj_kernel<<<go, 256>>>(Wo, bo, out);
}

// round 2
// speedup vs baseline: 3.0278x; 3.0278x over previous
#include <cuda_runtime.h>
#include <cstdint>

#define BB 8
#define SS 1024
#define DD 768
#define HH 16
#define HD 48
#define TOK (BB*SS)          // 8192
#define BHN (BB*HH)          // 128

// Scratch (static device arrays — no allocation allowed)
__device__ __align__(256) float g_q[BHN*SS*HD];
__device__ __align__(256) float g_k[BHN*SS*HD];
__device__ __align__(256) float g_v[BHN*SS*HD];
__device__ __align__(256) float g_ao[TOK*DD];

// ---------------------------------------------------------------------------
// tf32 helpers
// ---------------------------------------------------------------------------
__device__ __forceinline__ uint32_t f2tf(float x) {
    uint32_t u;
    asm("cvt.rna.tf32.f32 %0, %1;" : "=r"(u) : "f"(x));
    return u;
}

__device__ __forceinline__ void mma8(float c[4], const uint32_t a[4], const uint32_t b[2]) {
    asm volatile("mma.sync.aligned.m16n8k8.row.col.f32.tf32.tf32.f32 "
                 "{%0,%1,%2,%3}, {%4,%5,%6,%7}, {%8,%9}, {%0,%1,%2,%3};"
                 : "+f"(c[0]), "+f"(c[1]), "+f"(c[2]), "+f"(c[3])
                 : "r"(a[0]), "r"(a[1]), "r"(a[2]), "r"(a[3]),
                   "r"(b[0]), "r"(b[1]));
}

// ---------------------------------------------------------------------------
// GEMM core: C[128x128] tile of A[*,768] @ W[768,768].
// 256 threads = 8 warps, each warp 64x32. BK=32 (4 mma k-steps).
// As[128][36] (pad: LDS bank = 4g+tig, conflict-free)
// Bs[32][136] (pad: LDS bank = 8tig+g, conflict-free)
// smem holds tf32-pre-rounded values.
// ---------------------------------------------------------------------------
__device__ __forceinline__ void gemm_core(const float* __restrict__ A,
                                          const float* __restrict__ W,
                                          uint32_t* As, uint32_t* Bs,
                                          float acc[4][4][4],
                                          int m0, int n0)
{
    const int tid  = threadIdx.x;
    const int lane = tid & 31, warp = tid >> 5;
    const int g = lane >> 2, tig = lane & 3;
    const int wm = (warp >> 2) * 64, wn = (warp & 3) * 32;

    for (int kt = 0; kt < DD / 32; ++kt) {
        const int k0c = kt * 32;
        // A chunk 128x32 -> As
        #pragma unroll
        for (int it = 0; it < 4; ++it) {
            int f = tid + it * 256;
            int m = f >> 3, kq = f & 7;
            float4 v = *reinterpret_cast<const float4*>(
                &A[(size_t)(m0 + m) * DD + k0c + kq * 4]);
            uint4 w = make_uint4(f2tf(v.x), f2tf(v.y), f2tf(v.z), f2tf(v.w));
            *reinterpret_cast<uint4*>(&As[m * 36 + kq * 4]) = w;
        }
        // B chunk 32x128 -> Bs
        #pragma unroll
        for (int it = 0; it < 4; ++it) {
            int f = tid + it * 256;
            int k = f >> 5, nq = f & 31;
            float4 v = *reinterpret_cast<const float4*>(
                &W[(size_t)(k0c + k) * DD + n0 + nq * 4]);
            uint4 w = make_uint4(f2tf(v.x), f2tf(v.y), f2tf(v.z), f2tf(v.w));
            *reinterpret_cast<uint4*>(&Bs[k * 136 + nq * 4]) = w;
        }
        __syncthreads();
        #pragma unroll
        for (int kk = 0; kk < 4; ++kk) {
            const int k0 = kk * 8;
            uint32_t a[4][4], b[4][2];
            #pragma unroll
            for (int mi = 0; mi < 4; ++mi) {
                int r = wm + mi * 16;
                a[mi][0] = As[(r + g) * 36     + k0 + tig];
                a[mi][1] = As[(r + g + 8) * 36 + k0 + tig];
                a[mi][2] = As[(r + g) * 36     + k0 + tig + 4];
                a[mi][3] = As[(r + g + 8) * 36 + k0 + tig + 4];
            }
            #pragma unroll
            for (int ni = 0; ni < 4; ++ni) {
                int c = wn + ni * 8 + g;
                b[ni][0] = Bs[(k0 + tig) * 136     + c];
                b[ni][1] = Bs[(k0 + tig + 4) * 136 + c];
            }
            #pragma unroll
            for (int mi = 0; mi < 4; ++mi)
                #pragma unroll
                for (int ni = 0; ni < 4; ++ni)
                    mma8(acc[mi][ni], a[mi], b[ni]);
        }
        __syncthreads();
    }
}

// ---------------------------------------------------------------------------
// QKV projection (z selects Q/K/V), output remapped to [B*H, S, 48]
// ---------------------------------------------------------------------------
__global__ void __launch_bounds__(256, 2)
qkv_kernel(const float* __restrict__ x,
           const float* __restrict__ Wq, const float* __restrict__ bq,
           const float* __restrict__ Wk, const float* __restrict__ bk,
           const float* __restrict__ Wv, const float* __restrict__ bv)
{
    __shared__ uint32_t As[128 * 36];
    __shared__ uint32_t Bs[32 * 136];
    const int z = blockIdx.z;
    const float* W    = (z == 0) ? Wq : (z == 1) ? Wk : Wv;
    const float* bias = (z == 0) ? bq : (z == 1) ? bk : bv;
    float* out        = (z == 0) ? g_q : (z == 1) ? g_k : g_v;

    float acc[4][4][4] = {};
    const int m0 = blockIdx.x * 128, n0 = blockIdx.y * 128;
    gemm_core(x, W, As, Bs, acc, m0, n0);

    const int lane = threadIdx.x & 31, warp = threadIdx.x >> 5;
    const int g = lane >> 2, tig = lane & 3;
    const int wm = (warp >> 2) * 64, wn = (warp & 3) * 32;
    #pragma unroll
    for (int mi = 0; mi < 4; ++mi)
        #pragma unroll
        for (int ni = 0; ni < 4; ++ni)
            #pragma unroll
            for (int e = 0; e < 4; ++e) {
                int r = wm + mi * 16 + g + ((e >= 2) ? 8 : 0);
                int c = n0 + wn + ni * 8 + 2 * tig + (e & 1);
                int t = m0 + r;
                int bb = t >> 10, s = t & 1023;
                int h = c / HD, hd = c % HD;
                out[(((size_t)(bb * HH + h)) * SS + s) * HD + hd] =
                    acc[mi][ni][e] + bias[c];
            }
}

// ---------------------------------------------------------------------------
// Output projection: g_ao @ Wo + bo -> d_out
// ---------------------------------------------------------------------------
__global__ void __launch_bounds__(256, 2)
oproj_kernel(const float* __restrict__ Wo, const float* __restrict__ bo,
             float* __restrict__ out)
{
    __shared__ uint32_t As[128 * 36];
    __shared__ uint32_t Bs[32 * 136];
    float acc[4][4][4] = {};
    const int m0 = blockIdx.x * 128, n0 = blockIdx.y * 128;
    gemm_core(g_ao, Wo, As, Bs, acc, m0, n0);

    const int lane = threadIdx.x & 31, warp = threadIdx.x >> 5;
    const int g = lane >> 2, tig = lane & 3;
    const int wm = (warp >> 2) * 64, wn = (warp & 3) * 32;
    #pragma unroll
    for (int mi = 0; mi < 4; ++mi)
        #pragma unroll
        for (int ni = 0; ni < 4; ++ni)
            #pragma unroll
            for (int e = 0; e < 4; ++e) {
                int r = m0 + wm + mi * 16 + g + ((e >= 2) ? 8 : 0);
                int c = n0 + wn + ni * 8 + 2 * tig + (e & 1);
                out[(size_t)r * DD + c] = acc[mi][ni][e] + bo[c];
            }
}

// ---------------------------------------------------------------------------
// Flash attention, mma-based. CTA = (q-tile 64, bh). 256 thr = 8 warps.
//   Qs[64][52], Ks[64][52], Vs[64][56], Ps[64][68]  (pads: conflict-free frags)
// Scores: M64 N64 K48 (warp = m16 x n32). PV: M64 N48 K64 (warp = m16 x n24).
// ---------------------------------------------------------------------------
#define QSP 52
#define VSP 56
#define PSP 68

__global__ void __launch_bounds__(256)
attn_kernel()
{
    extern __shared__ float sm[];
    float* Qs   = sm;                    // 64*52
    float* Ks   = Qs + 64 * QSP;         // 64*52
    float* Vs   = Ks + 64 * QSP;         // 64*56
    float* Ps   = Vs + 64 * VSP;         // 64*68
    float* sm_m = Ps + 64 * PSP;
    float* sm_l = sm_m + 64;
    float* sm_c = sm_l + 64;

    const int tid  = threadIdx.x;
    const int lane = tid & 31, warp = tid >> 5;
    const int g = lane >> 2, tig = lane & 3;
    const int bh = blockIdx.y, q0 = blockIdx.x * 64;
    const float* qp = g_q + (size_t)bh * SS * HD;
    const float* kp = g_k + (size_t)bh * SS * HD;
    const float* vp = g_v + (size_t)bh * SS * HD;

    const int lr  = tid >> 2;           // load row 0..63
    const int ld0 = (tid & 3) * 12;     // 0,12,24,36

    // Load Q tile (tf32-rounded)
    {
        const float* src = qp + (size_t)(q0 + lr) * HD + ld0;
        #pragma unroll
        for (int v4 = 0; v4 < 3; ++v4) {
            float4 v = *reinterpret_cast<const float4*>(src + v4 * 4);
            Qs[lr * QSP + ld0 + v4 * 4 + 0] = __uint_as_float(f2tf(v.x));
            Qs[lr * QSP + ld0 + v4 * 4 + 1] = __uint_as_float(f2tf(v.y));
            Qs[lr * QSP + ld0 + v4 * 4 + 2] = __uint_as_float(f2tf(v.z));
            Qs[lr * QSP + ld0 + v4 * 4 + 3] = __uint_as_float(f2tf(v.w));
        }
    }
    if (tid < 64) { sm_m[tid] = -1e30f; sm_l[tid] = 0.f; }

    const int sw_m = (warp >> 1) * 16, sw_n = (warp & 1) * 32;  // scores
    const int pw_m = (warp >> 1) * 16, pw_n = (warp & 1) * 24;  // PV

    float o[3][4] = {};

    for (int kt = 0; kt < SS / 64; ++kt) {
        // Load K tile
        {
            const float* src = kp + (size_t)(kt * 64 + lr) * HD + ld0;
            #pragma unroll
            for (int v4 = 0; v4 < 3; ++v4) {
                float4 v = *reinterpret_cast<const float4*>(src + v4 * 4);
                Ks[lr * QSP + ld0 + v4 * 4 + 0] = __uint_as_float(f2tf(v.x));
                Ks[lr * QSP + ld0 + v4 * 4 + 1] = __uint_as_float(f2tf(v.y));
                Ks[lr * QSP + ld0 + v4 * 4 + 2] = __uint_as_float(f2tf(v.z));
                Ks[lr * QSP + ld0 + v4 * 4 + 3] = __uint_as_float(f2tf(v.w));
            }
        }
        __syncthreads();

        // Scores: S = Q K^T
        float s[4][4] = {};
        #pragma unroll
        for (int d0 = 0; d0 < 48; d0 += 8) {
            uint32_t a[4], b[4][2];
            a[0] = __float_as_uint(Qs[(sw_m + g) * QSP     + d0 + tig]);
            a[1] = __float_as_uint(Qs[(sw_m + g + 8) * QSP + d0 + tig]);
            a[2] = __float_as_uint(Qs[(sw_m + g) * QSP     + d0 + tig + 4]);
            a[3] = __float_as_uint(Qs[(sw_m + g + 8) * QSP + d0 + tig + 4]);
            #pragma unroll
            for (int ni = 0; ni < 4; ++ni) {
                int c = sw_n + ni * 8 + g;
                b[ni][0] = __float_as_uint(Ks[c * QSP + d0 + tig]);
                b[ni][1] = __float_as_uint(Ks[c * QSP + d0 + tig + 4]);
            }
            #pragma unroll
            for (int ni = 0; ni < 4; ++ni) mma8(s[ni], a, b[ni]);
        }
        const float sc = 0.14433756729740643f;   // 1/sqrt(48)
        #pragma unroll
        for (int ni = 0; ni < 4; ++ni) {
            int c = sw_n + ni * 8 + 2 * tig;
            Ps[(sw_m + g) * PSP + c]         = s[ni][0] * sc;
            Ps[(sw_m + g) * PSP + c + 1]     = s[ni][1] * sc;
            Ps[(sw_m + g + 8) * PSP + c]     = s[ni][2] * sc;
            Ps[(sw_m + g + 8) * PSP + c + 1] = s[ni][3] * sc;
        }
        // Load V tile (separate buffer; overlaps score epilogue)
        {
            const float* src = vp + (size_t)(kt * 64 + lr) * HD + ld0;
            #pragma unroll
            for (int v4 = 0; v4 < 3; ++v4) {
                float4 v = *reinterpret_cast<const float4*>(src + v4 * 4);
                Vs[lr * VSP + ld0 + v4 * 4 + 0] = __uint_as_float(f2tf(v.x));
                Vs[lr * VSP + ld0 + v4 * 4 + 1] = __uint_as_float(f2tf(v.y));
                Vs[lr * VSP + ld0 + v4 * 4 + 2] = __uint_as_float(f2tf(v.z));
                Vs[lr * VSP + ld0 + v4 * 4 + 3] = __uint_as_float(f2tf(v.w));
            }
        }
        __syncthreads();

        // Online softmax: 4 threads per row, 16 cols each
        {
            const int row = tid >> 2;
            const int j0  = (tid & 3) * 16;
            float mold = sm_m[row];
            float mx = mold;
            #pragma unroll
            for (int j = 0; j < 16; ++j) mx = fmaxf(mx, Ps[row * PSP + j0 + j]);
            mx = fmaxf(mx, __shfl_xor_sync(0xffffffffu, mx, 1));
            mx = fmaxf(mx, __shfl_xor_sync(0xffffffffu, mx, 2));
            float sum = 0.f;
            #pragma unroll
            for (int j = 0; j < 16; ++j) {
                float p = __expf(Ps[row * PSP + j0 + j] - mx);
                Ps[row * PSP + j0 + j] = __uint_as_float(f2tf(p));
                sum += p;
            }
            sum += __shfl_xor_sync(0xffffffffu, sum, 1);
            sum += __shfl_xor_sync(0xffffffffu, sum, 2);
            if ((tid & 3) == 0) {
                float corr = __expf(mold - mx);
                sm_c[row] = corr;
                sm_l[row] = sm_l[row] * corr + sum;
                sm_m[row] = mx;
            }
        }
        __syncthreads();

        // PV: O = corr*O + P @ V
        {
            const float c0 = sm_c[pw_m + g], c1 = sm_c[pw_m + g + 8];
            #pragma unroll
            for (int ni = 0; ni < 3; ++ni) {
                o[ni][0] *= c0; o[ni][1] *= c0;
                o[ni][2] *= c1; o[ni][3] *= c1;
            }
            #pragma unroll
            for (int k0 = 0; k0 < 64; k0 += 8) {
                uint32_t a[4], b[3][2];
                a[0] = __float_as_uint(Ps[(pw_m + g) * PSP     + k0 + tig]);
                a[1] = __float_as_uint(Ps[(pw_m + g + 8) * PSP + k0 + tig]);
                a[2] = __float_as_uint(Ps[(pw_m + g) * PSP     + k0 + tig + 4]);
                a[3] = __float_as_uint(Ps[(pw_m + g + 8) * PSP + k0 + tig + 4]);
                #pragma unroll
                for (int ni = 0; ni < 3; ++ni) {
                    int c = pw_n + ni * 8 + g;
                    b[ni][0] = __float_as_uint(Vs[(k0 + tig) * VSP     + c]);
                    b[ni][1] = __float_as_uint(Vs[(k0 + tig + 4) * VSP + c]);
                }
                #pragma unroll
                for (int ni = 0; ni < 3; ++ni) mma8(o[ni], a, b[ni]);
            }
        }
        __syncthreads();
    }

    // Epilogue: normalize, write to g_ao [B*S, 768] at head slot
    const float li0 = 1.f / sm_l[pw_m + g];
    const float li1 = 1.f / sm_l[pw_m + g + 8];
    const int bb = bh >> 4, h = bh & 15;
    #pragma unroll
    for (int ni = 0; ni < 3; ++ni) {
        int c  = h * HD + pw_n + ni * 8 + 2 * tig;
        int r0 = q0 + pw_m + g, r1 = r0 + 8;
        float* p0 = g_ao + ((size_t)(bb * SS + r0)) * DD + c;
        float* p1 = g_ao + ((size_t)(bb * SS + r1)) * DD + c;
        p0[0] = o[ni][0] * li0; p0[1] = o[ni][1] * li0;
        p1[0] = o[ni][2] * li1; p1[1] = o[ni][3] * li1;
    }
}

// ---------------------------------------------------------------------------
extern "C" void kernel_launch(void* const* d_in, const int* in_sizes, int n_in,
                              void* d_out, int out_size)
{
    const float* x  = (const float*)d_in[0];
    const float* Wq = (const float*)d_in[1];
    const float* bq = (const float*)d_in[2];
    const float* Wk = (const float*)d_in[3];
    const float* bk = (const float*)d_in[4];
    const float* Wv = (const float*)d_in[5];
    const float* bv = (const float*)d_in[6];
    const float* Wo = (const float*)d_in[7];
    const float* bo = (const float*)d_in[8];
    float* out = (float*)d_out;

    static const size_t attn_smem =
        (64 * QSP * 2 + 64 * VSP + 64 * PSP + 192) * sizeof(float);
    cudaFuncSetAttribute(attn_kernel,
                         cudaFuncAttributeMaxDynamicSharedMemorySize,
                         (int)attn_smem);

    dim3 gq(TOK / 128, DD / 128, 3);
    qkv_kernel<<<gq, 256>>>(x, Wq, bq, Wk, bk, Wv, bv);

    dim3 ga(SS / 64, BHN);
    attn_kernel<<<ga, 256, attn_smem>>>();

    dim3 go(TOK / 128, DD / 128);
    oproj_kernel<<<go, 256>>>(Wo, bo, out);
}